// round 2
// baseline (speedup 1.0000x reference)
#include <cuda_runtime.h>
#include <math.h>

#define N_NEWS  100000
#define N_ENT   50000
#define N_TOP   2000
#define DIM     128
#define N_EDGES 1600000
#define HID     512
#define OUTD    128

#define BM 64
#define KT 32

// ---------------- scratch (static device globals; no allocs allowed) ----------------
__device__ float g_ent_agg[(size_t)N_NEWS * DIM];   // 51.2 MB
__device__ float g_top_agg[(size_t)N_NEWS * DIM];   // 51.2 MB
__device__ int   g_ent_cnt[N_NEWS];
__device__ int   g_top_cnt[N_NEWS];
__device__ int   g_ent_cur[N_NEWS];
__device__ int   g_top_cur[N_NEWS];
__device__ int   g_ent_off[N_NEWS + 1];
__device__ int   g_top_off[N_NEWS + 1];
__device__ int   g_ent_dst[N_EDGES];
__device__ int   g_top_dst[N_EDGES];

// ---------------- K1: zero counters ----------------
__global__ void zero_kernel() {
    int i = blockIdx.x * blockDim.x + threadIdx.x;
    if (i < N_NEWS) {
        g_ent_cnt[i] = 0; g_top_cnt[i] = 0;
        g_ent_cur[i] = 0; g_top_cur[i] = 0;
    }
}

// ---------------- K2: degree histogram ----------------
__global__ void hist_kernel(const int* __restrict__ ent_row,
                            const int* __restrict__ top_row) {
    int i = blockIdx.x * blockDim.x + threadIdx.x;
    if (i < N_EDGES) {
        atomicAdd(&g_ent_cnt[ent_row[i]], 1);
        atomicAdd(&g_top_cnt[top_row[i]], 1);
    }
}

// ---------------- K3: exclusive scan (single block) ----------------
__device__ void scan_one(const int* __restrict__ cnt, int* __restrict__ off, int* s) {
    const int CH = (N_NEWS + 1023) / 1024;   // 98
    int t = threadIdx.x;
    int lo = t * CH;
    int hi = min(lo + CH, N_NEWS);
    int sum = 0;
    for (int i = lo; i < hi; i++) sum += cnt[i];
    s[t] = sum;
    __syncthreads();
    // inclusive Hillis-Steele scan over 1024 partials
    for (int d = 1; d < 1024; d <<= 1) {
        int v = (t >= d) ? s[t - d] : 0;
        __syncthreads();
        s[t] += v;
        __syncthreads();
    }
    int pre = (t > 0) ? s[t - 1] : 0;
    for (int i = lo; i < hi; i++) { off[i] = pre; pre += cnt[i]; }
    if (t == 1023) off[N_NEWS] = s[1023];
    __syncthreads();
}

__global__ void scan_kernel() {
    __shared__ int s[1024];
    scan_one(g_ent_cnt, g_ent_off, s);
    __syncthreads();
    scan_one(g_top_cnt, g_top_off, s);
}

// ---------------- K4: scatter edge targets into CSR ----------------
__global__ void scatter_kernel(const int* __restrict__ ent_row, const int* __restrict__ ent_col,
                               const int* __restrict__ top_row, const int* __restrict__ top_col) {
    int i = blockIdx.x * blockDim.x + threadIdx.x;
    if (i < N_EDGES) {
        int r = ent_row[i];
        int p = g_ent_off[r] + atomicAdd(&g_ent_cur[r], 1);
        g_ent_dst[p] = ent_col[i];
        r = top_row[i];
        p = g_top_off[r] + atomicAdd(&g_top_cur[r], 1);
        g_top_dst[p] = top_col[i];
    }
}

// ---------------- K5: gather-side segment mean (1 warp per node per relation) ----------------
__global__ void agg_kernel(const float* __restrict__ ent_feats,
                           const float* __restrict__ top_feats) {
    int w = (blockIdx.x * blockDim.x + threadIdx.x) >> 5;
    int lane = threadIdx.x & 31;
    if (w >= 2 * N_NEWS) return;

    const float* feats; const int* dst; const int* off; float* agg; int n;
    if (w < N_NEWS) { n = w;          feats = ent_feats; dst = g_ent_dst; off = g_ent_off; agg = g_ent_agg; }
    else            { n = w - N_NEWS; feats = top_feats; dst = g_top_dst; off = g_top_off; agg = g_top_agg; }

    int s = off[n], e = off[n + 1];
    float4 acc = make_float4(0.f, 0.f, 0.f, 0.f);
    for (int j = s; j < e; j++) {
        int c = dst[j];
        float4 v = *(const float4*)(feats + (size_t)c * DIM + lane * 4);
        acc.x += v.x; acc.y += v.y; acc.z += v.z; acc.w += v.w;
    }
    float inv = 1.0f / ((float)(e - s) + 1e-8f);
    float4 r = make_float4(acc.x * inv, acc.y * inv, acc.z * inv, acc.w * inv);
    *(float4*)(agg + (size_t)n * DIM + lane * 4) = r;
}

// ---------------- K6: fused concat + GEMM1 + tanh + GEMM2 ----------------
// 512 threads, BM=64 rows per block. Phase A: h = tanh(X[64x384] @ W1[384x512] + b1)
// kept in 128KB smem. Phase B: out = h @ W2[512x128] + b2.
// Thread map (both phases): ct = tid&31 (cols), rt = tid>>5 (4 rows each).
#define SMEM_FLOATS (BM * HID + KT * (BM + 1) + KT * HID)

__global__ __launch_bounds__(512, 1) void mlp_kernel(
    const float* __restrict__ news, const float* __restrict__ W1,
    const float* __restrict__ b1,   const float* __restrict__ W2,
    const float* __restrict__ b2,   float* __restrict__ out)
{
    extern __shared__ float smem[];
    float* Hs = smem;                      // BM x HID
    float* Xs = smem + BM * HID;           // KT x (BM+1), k-major, padded
    float* Ws = Xs + KT * (BM + 1);        // KT x HID (phase A) / KT x OUTD (phase B)

    int tid = threadIdx.x;
    int ct = tid & 31;
    int rt = tid >> 5;
    int row0 = blockIdx.x * BM;

    float acc[4][16];
#pragma unroll
    for (int r = 0; r < 4; r++)
#pragma unroll
        for (int j = 0; j < 16; j++) acc[r][j] = 0.f;

    for (int kt = 0; kt < 3 * DIM; kt += KT) {
        // select source column-block of the virtual concat
        const float* src; int kbase;
        if (kt < DIM)            { src = news;      kbase = kt; }
        else if (kt < 2 * DIM)   { src = g_ent_agg; kbase = kt - DIM; }
        else                     { src = g_top_agg; kbase = kt - 2 * DIM; }

        // load X tile (64 x 32) transposed into Xs[k][node]
        {
            int node = tid >> 3;            // 0..63
            int k4 = (tid & 7) * 4;         // 0..28
            int gnode = row0 + node;
            float4 v = make_float4(0.f, 0.f, 0.f, 0.f);
            if (gnode < N_NEWS)
                v = *(const float4*)(src + (size_t)gnode * DIM + kbase + k4);
            Xs[(k4 + 0) * (BM + 1) + node] = v.x;
            Xs[(k4 + 1) * (BM + 1) + node] = v.y;
            Xs[(k4 + 2) * (BM + 1) + node] = v.z;
            Xs[(k4 + 3) * (BM + 1) + node] = v.w;
        }
        // load W1 tile (32 x 512) flat
        {
            const float4* g = (const float4*)(W1 + (size_t)kt * HID);
            float4* s4 = (float4*)Ws;
#pragma unroll
            for (int j = 0; j < 8; j++) s4[tid + 512 * j] = g[tid + 512 * j];
        }
        __syncthreads();

#pragma unroll
        for (int k = 0; k < KT; k++) {
            float x0 = Xs[k * (BM + 1) + rt * 4 + 0];
            float x1 = Xs[k * (BM + 1) + rt * 4 + 1];
            float x2 = Xs[k * (BM + 1) + rt * 4 + 2];
            float x3 = Xs[k * (BM + 1) + rt * 4 + 3];
            const float4* wrow = (const float4*)(Ws + k * HID);
#pragma unroll
            for (int q = 0; q < 4; q++) {
                float4 w = wrow[ct + 32 * q];
                acc[0][q * 4 + 0] += x0 * w.x; acc[0][q * 4 + 1] += x0 * w.y;
                acc[0][q * 4 + 2] += x0 * w.z; acc[0][q * 4 + 3] += x0 * w.w;
                acc[1][q * 4 + 0] += x1 * w.x; acc[1][q * 4 + 1] += x1 * w.y;
                acc[1][q * 4 + 2] += x1 * w.z; acc[1][q * 4 + 3] += x1 * w.w;
                acc[2][q * 4 + 0] += x2 * w.x; acc[2][q * 4 + 1] += x2 * w.y;
                acc[2][q * 4 + 2] += x2 * w.z; acc[2][q * 4 + 3] += x2 * w.w;
                acc[3][q * 4 + 0] += x3 * w.x; acc[3][q * 4 + 1] += x3 * w.y;
                acc[3][q * 4 + 2] += x3 * w.z; acc[3][q * 4 + 3] += x3 * w.w;
            }
        }
        __syncthreads();
    }

    // bias + tanh -> Hs
#pragma unroll
    for (int q = 0; q < 4; q++) {
        int cbase = ct * 4 + 128 * q;
        float4 bb = *(const float4*)(b1 + cbase);
#pragma unroll
        for (int r = 0; r < 4; r++) {
            float4 h;
            h.x = tanhf(acc[r][q * 4 + 0] + bb.x);
            h.y = tanhf(acc[r][q * 4 + 1] + bb.y);
            h.z = tanhf(acc[r][q * 4 + 2] + bb.z);
            h.w = tanhf(acc[r][q * 4 + 3] + bb.w);
            *(float4*)(Hs + (rt * 4 + r) * HID + cbase) = h;
        }
    }
    __syncthreads();

    // Phase B: out = Hs @ W2 + b2
    float acc2[4][4];
#pragma unroll
    for (int r = 0; r < 4; r++)
#pragma unroll
        for (int j = 0; j < 4; j++) acc2[r][j] = 0.f;

    for (int k2 = 0; k2 < HID; k2 += KT) {
        // load W2 tile (32 x 128)
        const float4* g2 = (const float4*)(W2 + (size_t)k2 * OUTD);
        float4* s4 = (float4*)Ws;
        s4[tid] = g2[tid];
        s4[tid + 512] = g2[tid + 512];
        __syncthreads();
#pragma unroll
        for (int k = 0; k < KT; k++) {
            float4 w = ((const float4*)(Ws + k * OUTD))[ct];
            float x0 = Hs[(rt * 4 + 0) * HID + k2 + k];
            float x1 = Hs[(rt * 4 + 1) * HID + k2 + k];
            float x2 = Hs[(rt * 4 + 2) * HID + k2 + k];
            float x3 = Hs[(rt * 4 + 3) * HID + k2 + k];
            acc2[0][0] += x0 * w.x; acc2[0][1] += x0 * w.y; acc2[0][2] += x0 * w.z; acc2[0][3] += x0 * w.w;
            acc2[1][0] += x1 * w.x; acc2[1][1] += x1 * w.y; acc2[1][2] += x1 * w.z; acc2[1][3] += x1 * w.w;
            acc2[2][0] += x2 * w.x; acc2[2][1] += x2 * w.y; acc2[2][2] += x2 * w.z; acc2[2][3] += x2 * w.w;
            acc2[3][0] += x3 * w.x; acc2[3][1] += x3 * w.y; acc2[3][2] += x3 * w.z; acc2[3][3] += x3 * w.w;
        }
        __syncthreads();
    }

    float4 bb2 = *(const float4*)(b2 + ct * 4);
#pragma unroll
    for (int r = 0; r < 4; r++) {
        int gnode = row0 + rt * 4 + r;
        if (gnode < N_NEWS) {
            float4 o;
            o.x = acc2[r][0] + bb2.x;
            o.y = acc2[r][1] + bb2.y;
            o.z = acc2[r][2] + bb2.z;
            o.w = acc2[r][3] + bb2.w;
            *(float4*)(out + (size_t)gnode * OUTD + ct * 4) = o;
        }
    }
}

// ---------------- launch ----------------
extern "C" void kernel_launch(void* const* d_in, const int* in_sizes, int n_in,
                              void* d_out, int out_size) {
    const float* news    = (const float*)d_in[0];
    const float* entf    = (const float*)d_in[1];
    const float* topf    = (const float*)d_in[2];
    const int*   ent_row = (const int*)d_in[3];
    const int*   ent_col = (const int*)d_in[4];
    const int*   top_row = (const int*)d_in[5];
    const int*   top_col = (const int*)d_in[6];
    const float* W1      = (const float*)d_in[7];
    const float* b1      = (const float*)d_in[8];
    const float* W2      = (const float*)d_in[9];
    const float* b2      = (const float*)d_in[10];
    float* out = (float*)d_out;

    size_t smem_bytes = (size_t)SMEM_FLOATS * sizeof(float);   // ~200 KB
    cudaFuncSetAttribute(mlp_kernel, cudaFuncAttributeMaxDynamicSharedMemorySize,
                         (int)smem_bytes);

    zero_kernel<<<(N_NEWS + 255) / 256, 256>>>();
    hist_kernel<<<(N_EDGES + 255) / 256, 256>>>(ent_row, top_row);
    scan_kernel<<<1, 1024>>>();
    scatter_kernel<<<(N_EDGES + 255) / 256, 256>>>(ent_row, ent_col, top_row, top_col);
    agg_kernel<<<(2 * N_NEWS * 32 + 255) / 256, 256>>>(entf, topf);
    mlp_kernel<<<(N_NEWS + BM - 1) / BM, 512, smem_bytes>>>(news, W1, b1, W2, b2, out);
}

// round 7
// speedup vs baseline: 1.6138x; 1.6138x over previous
#include <cuda_runtime.h>
#include <cuda_bf16.h>
#include <cstdint>
#include <math.h>

#define N_NEWS  100000
#define N_PAD   100096
#define N_ENT   50000
#define N_TOP   2000
#define DIM     128
#define N_EDGES 1600000
#define HID     512
#define OUTD    128
#define KTOT    384

// ---------------- scratch (static device globals; zero-initialized) ----------------
__device__ int   g_ent_cnt[N_NEWS];
__device__ int   g_top_cnt[N_NEWS];
__device__ int   g_ent_cur[N_NEWS];
__device__ int   g_top_cur[N_NEWS];
__device__ int   g_ent_off[N_NEWS + 1];
__device__ int   g_top_off[N_NEWS + 1];
__device__ int   g_ent_dst[N_EDGES];
__device__ int   g_top_dst[N_EDGES];

// bf16 split operand buffers (padding rows stay zero: device globals are zero-init
// and rows >= N_NEWS are never written)
__device__ __align__(16) __nv_bfloat16 g_Xhi[(size_t)N_PAD * KTOT];
__device__ __align__(16) __nv_bfloat16 g_Xlo[(size_t)N_PAD * KTOT];
__device__ __align__(16) __nv_bfloat16 g_W1T_hi[HID * KTOT];
__device__ __align__(16) __nv_bfloat16 g_W1T_lo[HID * KTOT];
__device__ __align__(16) __nv_bfloat16 g_W2T_hi[OUTD * HID];
__device__ __align__(16) __nv_bfloat16 g_W2T_lo[OUTD * HID];

// ---------------- helpers ----------------
static __device__ __forceinline__ unsigned pack2f(float a, float b) {
    __nv_bfloat162 t = __floats2bfloat162_rn(a, b);
    return *reinterpret_cast<unsigned*>(&t);
}
static __device__ __forceinline__ float rtb(float x) {
    return __bfloat162float(__float2bfloat16_rn(x));
}

// m16n8k16 row.col bf16 -> f32 accumulate (HMMA on sm_103 base target)
static __device__ __forceinline__ void mma16816(float* d, const uint32_t* a, const uint32_t* b) {
    asm volatile(
        "mma.sync.aligned.m16n8k16.row.col.f32.bf16.bf16.f32 "
        "{%0,%1,%2,%3}, {%4,%5,%6,%7}, {%8,%9}, {%0,%1,%2,%3};"
        : "+f"(d[0]), "+f"(d[1]), "+f"(d[2]), "+f"(d[3])
        : "r"(a[0]), "r"(a[1]), "r"(a[2]), "r"(a[3]), "r"(b[0]), "r"(b[1]));
}

// ---------------- CSR build ----------------
__global__ void zero_kernel() {
    int i = blockIdx.x * blockDim.x + threadIdx.x;
    if (i < N_NEWS) {
        g_ent_cnt[i] = 0; g_top_cnt[i] = 0;
        g_ent_cur[i] = 0; g_top_cur[i] = 0;
    }
}

__global__ void hist_kernel(const int* __restrict__ ent_row,
                            const int* __restrict__ top_row) {
    int i = blockIdx.x * blockDim.x + threadIdx.x;
    if (i < N_EDGES) {
        atomicAdd(&g_ent_cnt[ent_row[i]], 1);
        atomicAdd(&g_top_cnt[top_row[i]], 1);
    }
}

__device__ void scan_one(const int* __restrict__ cnt, int* __restrict__ off, int* s) {
    const int CH = (N_NEWS + 1023) / 1024;
    int t = threadIdx.x;
    int lo = t * CH;
    int hi = min(lo + CH, N_NEWS);
    int sum = 0;
    for (int i = lo; i < hi; i++) sum += cnt[i];
    s[t] = sum;
    __syncthreads();
    for (int d = 1; d < 1024; d <<= 1) {
        int v = (t >= d) ? s[t - d] : 0;
        __syncthreads();
        s[t] += v;
        __syncthreads();
    }
    int pre = (t > 0) ? s[t - 1] : 0;
    for (int i = lo; i < hi; i++) { off[i] = pre; pre += cnt[i]; }
    if (t == 1023) off[N_NEWS] = s[1023];
    __syncthreads();
}

__global__ void scan_kernel() {
    __shared__ int s[1024];
    scan_one(g_ent_cnt, g_ent_off, s);
    __syncthreads();
    scan_one(g_top_cnt, g_top_off, s);
}

__global__ void scatter_kernel(const int* __restrict__ ent_row, const int* __restrict__ ent_col,
                               const int* __restrict__ top_row, const int* __restrict__ top_col) {
    int i = blockIdx.x * blockDim.x + threadIdx.x;
    if (i < N_EDGES) {
        int r = ent_row[i];
        int p = g_ent_off[r] + atomicAdd(&g_ent_cur[r], 1);
        g_ent_dst[p] = ent_col[i];
        r = top_row[i];
        p = g_top_off[r] + atomicAdd(&g_top_cur[r], 1);
        g_top_dst[p] = top_col[i];
    }
}

// ---------------- segment mean -> bf16 hi/lo into X cols 128..383 ----------------
__global__ void agg_kernel(const float* __restrict__ ent_feats,
                           const float* __restrict__ top_feats) {
    int w = (blockIdx.x * blockDim.x + threadIdx.x) >> 5;
    int lane = threadIdx.x & 31;
    if (w >= 2 * N_NEWS) return;

    const float* feats; const int* dst; const int* off; int n, coff;
    if (w < N_NEWS) { n = w;          feats = ent_feats; dst = g_ent_dst; off = g_ent_off; coff = 128; }
    else            { n = w - N_NEWS; feats = top_feats; dst = g_top_dst; off = g_top_off; coff = 256; }

    int s = off[n], e = off[n + 1];
    float4 acc = make_float4(0.f, 0.f, 0.f, 0.f);
    for (int j = s; j < e; j++) {
        int c = dst[j];
        float4 v = *(const float4*)(feats + (size_t)c * DIM + lane * 4);
        acc.x += v.x; acc.y += v.y; acc.z += v.z; acc.w += v.w;
    }
    float inv = 1.0f / ((float)(e - s) + 1e-8f);
    float rx = acc.x * inv, ry = acc.y * inv, rz = acc.z * inv, rw = acc.w * inv;

    size_t base = (size_t)n * KTOT + coff + lane * 4;
    uint2 hv, lv;
    hv.x = pack2f(rx, ry); hv.y = pack2f(rz, rw);
    lv.x = pack2f(rx - rtb(rx), ry - rtb(ry));
    lv.y = pack2f(rz - rtb(rz), rw - rtb(rw));
    *(uint2*)(g_Xhi + base) = hv;
    *(uint2*)(g_Xlo + base) = lv;
}

// ---------------- news features -> X cols 0..127 ----------------
__global__ void convert_news_kernel(const float* __restrict__ news) {
    int i = blockIdx.x * blockDim.x + threadIdx.x;
    if (i >= N_NEWS * 32) return;
    int row = i >> 5, q = i & 31;
    float4 v = ((const float4*)news)[i];
    size_t base = (size_t)row * KTOT + q * 4;
    uint2 hv, lv;
    hv.x = pack2f(v.x, v.y); hv.y = pack2f(v.z, v.w);
    lv.x = pack2f(v.x - rtb(v.x), v.y - rtb(v.y));
    lv.y = pack2f(v.z - rtb(v.z), v.w - rtb(v.w));
    *(uint2*)(g_Xhi + base) = hv;
    *(uint2*)(g_Xlo + base) = lv;
}

// ---------------- transpose + split weights ----------------
__global__ void prep_w_kernel(const float* __restrict__ W1, const float* __restrict__ W2) {
    int i = blockIdx.x * blockDim.x + threadIdx.x;
    if (i < KTOT * HID) {                       // W1 [384][512] -> W1T [512][384]
        int k = i >> 9, n = i & 511;
        float v = W1[i];
        g_W1T_hi[n * KTOT + k] = __float2bfloat16_rn(v);
        g_W1T_lo[n * KTOT + k] = __float2bfloat16_rn(v - rtb(v));
    } else if (i < KTOT * HID + HID * OUTD) {   // W2 [512][128] -> W2T [128][512]
        int j = i - KTOT * HID;
        int k = j >> 7, c = j & 127;
        float v = W2[j];
        g_W2T_hi[c * HID + k] = __float2bfloat16_rn(v);
        g_W2T_lo[c * HID + k] = __float2bfloat16_rn(v - rtb(v));
    }
}

// ---------------- fused MLP via mma.sync (HMMA), 3-pass bf16 split ----------------
// smem (bf16 elems): Xh/Xl [128][40], Wh/Wl [256][40], Hh/Hl [128][264]
#define PX 40
#define PH 264
#define SMEM_BF16 (2 * 128 * PX + 2 * 256 * PX + 2 * 128 * PH)   // 98304 elems = 196608 B

__global__ __launch_bounds__(512, 1) void mlp_mma_kernel(
    const float* __restrict__ b1, const float* __restrict__ b2, float* __restrict__ out)
{
    extern __shared__ __align__(16) __nv_bfloat16 smem[];
    __nv_bfloat16* Xh = smem;
    __nv_bfloat16* Xl = Xh + 128 * PX;
    __nv_bfloat16* Wh = Xl + 128 * PX;
    __nv_bfloat16* Wl = Wh + 256 * PX;
    __nv_bfloat16* Hh = Wl + 256 * PX;
    __nv_bfloat16* Hl = Hh + 128 * PH;

    int tid = threadIdx.x;
    int wid = tid >> 5, lane = tid & 31;
    int g = lane >> 2, i4 = lane & 3;
    int wm = wid >> 2, wn = wid & 3;
    int row0 = blockIdx.x * 128;

    float e[2][4][4];
#pragma unroll
    for (int mt = 0; mt < 2; mt++)
#pragma unroll
        for (int nt = 0; nt < 4; nt++)
#pragma unroll
            for (int q = 0; q < 4; q++) e[mt][nt][q] = 0.f;

    for (int h = 0; h < 2; h++) {
        // ======== GEMM1 half: D1[128x256] = X[128x384] @ W1T_half^T ========
        float d[2][8][4];
#pragma unroll
        for (int mt = 0; mt < 2; mt++)
#pragma unroll
            for (int nt = 0; nt < 8; nt++)
#pragma unroll
                for (int q = 0; q < 4; q++) d[mt][nt][q] = 0.f;

        for (int kc = 0; kc < 12; kc++) {
            // load X chunk [128][32] hi/lo
#pragma unroll
            for (int idx = tid; idx < 1024; idx += 512) {
                int r = idx >> 3, j = idx & 7;
                size_t go = (size_t)(row0 + r) * KTOT + kc * 32 + j * 4;
                *(uint2*)(Xh + r * PX + j * 4) = *(const uint2*)(g_Xhi + go);
                *(uint2*)(Xl + r * PX + j * 4) = *(const uint2*)(g_Xlo + go);
            }
            // load W1 chunk [256][32] hi/lo
#pragma unroll
            for (int idx = tid; idx < 2048; idx += 512) {
                int r = idx >> 3, j = idx & 7;
                size_t go = (size_t)(h * 256 + r) * KTOT + kc * 32 + j * 4;
                *(uint2*)(Wh + r * PX + j * 4) = *(const uint2*)(g_W1T_hi + go);
                *(uint2*)(Wl + r * PX + j * 4) = *(const uint2*)(g_W1T_lo + go);
            }
            __syncthreads();

#pragma unroll
            for (int ks = 0; ks < 2; ks++) {
                int kb = ks * 16;
                uint32_t ah[2][4], al[2][4];
#pragma unroll
                for (int mt = 0; mt < 2; mt++) {
                    const __nv_bfloat16* ph = Xh + (wm * 32 + mt * 16 + g) * PX + kb + 2 * i4;
                    const __nv_bfloat16* pl = Xl + (wm * 32 + mt * 16 + g) * PX + kb + 2 * i4;
                    ah[mt][0] = *(const uint32_t*)ph;
                    ah[mt][1] = *(const uint32_t*)(ph + 8 * PX);
                    ah[mt][2] = *(const uint32_t*)(ph + 8);
                    ah[mt][3] = *(const uint32_t*)(ph + 8 * PX + 8);
                    al[mt][0] = *(const uint32_t*)pl;
                    al[mt][1] = *(const uint32_t*)(pl + 8 * PX);
                    al[mt][2] = *(const uint32_t*)(pl + 8);
                    al[mt][3] = *(const uint32_t*)(pl + 8 * PX + 8);
                }
#pragma unroll
                for (int nt = 0; nt < 8; nt++) {
                    const __nv_bfloat16* pbh = Wh + (wn * 64 + nt * 8 + g) * PX + kb + 2 * i4;
                    const __nv_bfloat16* pbl = Wl + (wn * 64 + nt * 8 + g) * PX + kb + 2 * i4;
                    uint32_t bh[2] = { *(const uint32_t*)pbh, *(const uint32_t*)(pbh + 8) };
                    uint32_t bl[2] = { *(const uint32_t*)pbl, *(const uint32_t*)(pbl + 8) };
#pragma unroll
                    for (int mt = 0; mt < 2; mt++) {
                        mma16816(d[mt][nt], ah[mt], bh);
                        mma16816(d[mt][nt], al[mt], bh);
                        mma16816(d[mt][nt], ah[mt], bl);
                    }
                }
            }
            __syncthreads();
        }

        // ======== epilogue1: tanh(D1 + b1) -> H hi/lo in smem ========
#pragma unroll
        for (int mt = 0; mt < 2; mt++) {
#pragma unroll
            for (int nt = 0; nt < 8; nt++) {
                int rr = wm * 32 + mt * 16 + g;
                int cc = wn * 64 + nt * 8 + 2 * i4;
                int n = h * 256 + cc;
                float bb0 = __ldg(&b1[n]), bb1 = __ldg(&b1[n + 1]);
                float t0 = tanhf(d[mt][nt][0] + bb0);
                float t1 = tanhf(d[mt][nt][1] + bb1);
                *(uint32_t*)(Hh + rr * PH + cc) = pack2f(t0, t1);
                *(uint32_t*)(Hl + rr * PH + cc) = pack2f(t0 - rtb(t0), t1 - rtb(t1));
                t0 = tanhf(d[mt][nt][2] + bb0);
                t1 = tanhf(d[mt][nt][3] + bb1);
                *(uint32_t*)(Hh + (rr + 8) * PH + cc) = pack2f(t0, t1);
                *(uint32_t*)(Hl + (rr + 8) * PH + cc) = pack2f(t0 - rtb(t0), t1 - rtb(t1));
            }
        }
        __syncthreads();

        // ======== GEMM2 partial: D2[128x128] += H_half[128x256] @ W2_half ========
        for (int kc2 = 0; kc2 < 8; kc2++) {
#pragma unroll
            for (int idx = tid; idx < 1024; idx += 512) {
                int r = idx >> 3, j = idx & 7;
                size_t go = (size_t)r * HID + h * 256 + kc2 * 32 + j * 4;
                *(uint2*)(Wh + r * PX + j * 4) = *(const uint2*)(g_W2T_hi + go);
                *(uint2*)(Wl + r * PX + j * 4) = *(const uint2*)(g_W2T_lo + go);
            }
            __syncthreads();

#pragma unroll
            for (int ks = 0; ks < 2; ks++) {
                int kbH = kc2 * 32 + ks * 16;   // H column index
                int kbW = ks * 16;              // chunk-local k
                uint32_t ah[2][4], al[2][4];
#pragma unroll
                for (int mt = 0; mt < 2; mt++) {
                    const __nv_bfloat16* ph = Hh + (wm * 32 + mt * 16 + g) * PH + kbH + 2 * i4;
                    const __nv_bfloat16* pl = Hl + (wm * 32 + mt * 16 + g) * PH + kbH + 2 * i4;
                    ah[mt][0] = *(const uint32_t*)ph;
                    ah[mt][1] = *(const uint32_t*)(ph + 8 * PH);
                    ah[mt][2] = *(const uint32_t*)(ph + 8);
                    ah[mt][3] = *(const uint32_t*)(ph + 8 * PH + 8);
                    al[mt][0] = *(const uint32_t*)pl;
                    al[mt][1] = *(const uint32_t*)(pl + 8 * PH);
                    al[mt][2] = *(const uint32_t*)(pl + 8);
                    al[mt][3] = *(const uint32_t*)(pl + 8 * PH + 8);
                }
#pragma unroll
                for (int nt = 0; nt < 4; nt++) {
                    const __nv_bfloat16* pbh = Wh + (wn * 32 + nt * 8 + g) * PX + kbW + 2 * i4;
                    const __nv_bfloat16* pbl = Wl + (wn * 32 + nt * 8 + g) * PX + kbW + 2 * i4;
                    uint32_t bh[2] = { *(const uint32_t*)pbh, *(const uint32_t*)(pbh + 8) };
                    uint32_t bl[2] = { *(const uint32_t*)pbl, *(const uint32_t*)(pbl + 8) };
#pragma unroll
                    for (int mt = 0; mt < 2; mt++) {
                        mma16816(e[mt][nt], ah[mt], bh);
                        mma16816(e[mt][nt], al[mt], bh);
                        mma16816(e[mt][nt], ah[mt], bl);
                    }
                }
            }
            __syncthreads();
        }
    }

    // ======== epilogue2: out = D2 + b2 ========
#pragma unroll
    for (int mt = 0; mt < 2; mt++) {
#pragma unroll
        for (int nt = 0; nt < 4; nt++) {
            int rr = wm * 32 + mt * 16 + g;
            int cc = wn * 32 + nt * 8 + 2 * i4;
            float bb0 = __ldg(&b2[cc]), bb1 = __ldg(&b2[cc + 1]);
            int gr = row0 + rr;
            if (gr < N_NEWS) {
                float2 o = make_float2(e[mt][nt][0] + bb0, e[mt][nt][1] + bb1);
                *(float2*)(out + (size_t)gr * OUTD + cc) = o;
            }
            gr += 8;
            if (gr < N_NEWS) {
                float2 o = make_float2(e[mt][nt][2] + bb0, e[mt][nt][3] + bb1);
                *(float2*)(out + (size_t)gr * OUTD + cc) = o;
            }
        }
    }
}

// ---------------- launch ----------------
extern "C" void kernel_launch(void* const* d_in, const int* in_sizes, int n_in,
                              void* d_out, int out_size) {
    const float* news    = (const float*)d_in[0];
    const float* entf    = (const float*)d_in[1];
    const float* topf    = (const float*)d_in[2];
    const int*   ent_row = (const int*)d_in[3];
    const int*   ent_col = (const int*)d_in[4];
    const int*   top_row = (const int*)d_in[5];
    const int*   top_col = (const int*)d_in[6];
    const float* W1      = (const float*)d_in[7];
    const float* b1      = (const float*)d_in[8];
    const float* W2      = (const float*)d_in[9];
    const float* b2      = (const float*)d_in[10];
    float* out = (float*)d_out;

    size_t smem_bytes = (size_t)SMEM_BF16 * sizeof(__nv_bfloat16);   // 196608
    cudaFuncSetAttribute(mlp_mma_kernel, cudaFuncAttributeMaxDynamicSharedMemorySize,
                         (int)smem_bytes);

    zero_kernel<<<(N_NEWS + 255) / 256, 256>>>();
    hist_kernel<<<(N_EDGES + 255) / 256, 256>>>(ent_row, top_row);
    scan_kernel<<<1, 1024>>>();
    scatter_kernel<<<(N_EDGES + 255) / 256, 256>>>(ent_row, ent_col, top_row, top_col);
    agg_kernel<<<(2 * N_NEWS * 32 + 255) / 256, 256>>>(entf, topf);
    convert_news_kernel<<<(N_NEWS * 32 + 255) / 256, 256>>>(news);
    prep_w_kernel<<<(KTOT * HID + HID * OUTD + 255) / 256, 256>>>(W1, W2);

    mlp_mma_kernel<<<N_PAD / 128, 512, smem_bytes>>>(b1, b2, out);
}